// round 15
// baseline (speedup 1.0000x reference)
#include <cuda_runtime.h>
#include <cuda_fp16.h>
#include <mma.h>
#include <math.h>

using namespace nvcuda;

#define NN 50000
#define EMAXE 900000
#define NCHUNK 4
#define CH 12544   // chunk size (multiple of 128); last chunk = NN - 3*CH = 12368

// ---------------- scratch (device globals) -----------------------------------
__device__ __half g_xh[(size_t)NN * 128];    // x in fp16 (GEMM0 A)
__device__ __half g_W0h[128 * 256];
__device__ __half g_W1h[256 * 128];
__device__ __half g_h0[(size_t)NN * 256];    // layer0 features, fp16
__device__ __half g_out0h[(size_t)NN * 256]; // layer0 output, fp16 (GEMM1 A)
__device__ __half g_h1[(size_t)NN * 128];    // layer1 features, fp16
__device__ float  g_ssrc0[NN * 2];
__device__ float  g_sdst0[NN * 2];
__device__ float  g_ssrc1[NN];
__device__ float  g_sdst1[NN];
__device__ int    g_cnt[NN];
__device__ int    g_off[NN + 1];
__device__ int    g_cursor[NN];
__device__ int    g_csrc[EMAXE];

__device__ __forceinline__ float lrelu(float v) { return v > 0.f ? v : 0.2f * v; }

// ---------------- fp32 -> fp16 convert ----------------------------------------
__global__ void f2h(const float* __restrict__ in, __half* __restrict__ out, int n4) {
    int i = blockIdx.x * blockDim.x + threadIdx.x;
    if (i < n4) {
        float4 v = ((const float4*)in)[i];
        __half2 p0 = __floats2half2_rn(v.x, v.y);
        __half2 p1 = __floats2half2_rn(v.z, v.w);
        ((uint2*)out)[i] = make_uint2(*(unsigned*)&p0, *(unsigned*)&p1);
    }
}

// ---------------- CSR build ---------------------------------------------------
__global__ void filli(int* __restrict__ p, int n, int v) {
    int i = blockIdx.x * blockDim.x + threadIdx.x;
    if (i < n) p[i] = v;
}

__global__ void histK(const int* __restrict__ dst, int E0, int* __restrict__ cnt) {
    int e = blockIdx.x * blockDim.x + threadIdx.x;
    if (e < E0) atomicAdd(&cnt[dst[e]], 1);
}

__global__ __launch_bounds__(1024) void scanK(const int* __restrict__ cnt,
                                              int* __restrict__ off,
                                              int* __restrict__ cursor) {
    __shared__ int wsum[32];
    __shared__ int s_carry;
    int tid = threadIdx.x;
    int lane = tid & 31, warp = tid >> 5;
    if (tid == 0) s_carry = 0;
    __syncthreads();
    for (int base = 0; base < NN; base += 1024) {
        int i = base + tid;
        int v = (i < NN) ? cnt[i] : 0;
        int s = v;
#pragma unroll
        for (int o = 1; o < 32; o <<= 1) {
            int t = __shfl_up_sync(0xffffffffu, s, o);
            if (lane >= o) s += t;
        }
        if (lane == 31) wsum[warp] = s;
        __syncthreads();
        if (warp == 0) {
            int ws = wsum[lane];
#pragma unroll
            for (int o = 1; o < 32; o <<= 1) {
                int t = __shfl_up_sync(0xffffffffu, ws, o);
                if (lane >= o) ws += t;
            }
            wsum[lane] = ws;
        }
        __syncthreads();
        int excl = s - v + (warp ? wsum[warp - 1] : 0) + s_carry;
        if (i < NN) { off[i] = excl; cursor[i] = excl; }
        __syncthreads();
        if (tid == 1023) s_carry = excl + v;
        __syncthreads();
    }
    if (tid == 0) off[NN] = s_carry;
}

__global__ void scatterK(const int* __restrict__ src, const int* __restrict__ dst,
                         int E0, int Etot, int* __restrict__ cursor,
                         int* __restrict__ csrc) {
    int e = blockIdx.x * blockDim.x + threadIdx.x;
    if (e >= Etot) return;
    int s, d;
    if (e < E0) { s = src[e]; d = dst[e]; } else { s = d = e - E0; }
    int p = atomicAdd(&cursor[d], 1);
    csrc[p] = s;
}

// ---------------- tensor-core GEMM + fused scores ------------------------------
// A/B fp16, acc fp32, C out fp16. 128x128 tile, 8 warps (64x32 each),
// single-buffered smem (R12-proven). Epilogue stages fp32 C tile in smem for
// the a_src/a_dst score reduction and the fp16 C store.
#define SMA 24
#define SMB 136
#define SMC 132
#define GEMM_SMEM (128 * SMC * 4)

__global__ __launch_bounds__(256) void gemmW(const __half* __restrict__ A,
                                             const __half* __restrict__ B,
                                             __half* __restrict__ C,
                                             const float* __restrict__ a_src,
                                             const float* __restrict__ a_dst,
                                             float* __restrict__ ssrc,
                                             float* __restrict__ sdst,
                                             int M, int N, int K, int H,
                                             int rowBase) {
    extern __shared__ char smem[];
    __half* sA = (__half*)smem;                    // [128][SMA]
    __half* sB = (__half*)(smem + 128 * SMA * 2);  // [16][SMB]
    float*  sC = (float*)smem;                     // [128][SMC] (post-loop)

    int bm = rowBase + blockIdx.y * 128, bn = blockIdx.x * 128;
    int head = blockIdx.x;
    int tid = threadIdx.x;
    int wid = tid >> 5;
    int wm = wid >> 2, wn = wid & 3;

    wmma::fragment<wmma::accumulator, 16, 16, 16, float> fc[4][2];
#pragma unroll
    for (int i = 0; i < 4; i++)
#pragma unroll
        for (int j = 0; j < 2; j++) wmma::fill_fragment(fc[i][j], 0.f);

    int raA = tid >> 1, caA = (tid & 1) * 8;
    int raB = tid >> 4, caB = (tid & 15) * 8;

    for (int k0 = 0; k0 < K; k0 += 16) {
        __syncthreads();
        {
            uint4 v = make_uint4(0, 0, 0, 0);
            if (bm + raA < M)
                v = *(const uint4*)(A + (size_t)(bm + raA) * K + k0 + caA);
            *(uint4*)(sA + raA * SMA + caA) = v;
            uint4 w = *(const uint4*)(B + (size_t)(k0 + raB) * N + bn + caB);
            *(uint4*)(sB + raB * SMB + caB) = w;
        }
        __syncthreads();
        wmma::fragment<wmma::matrix_b, 16, 16, 16, __half, wmma::row_major> fb[2];
#pragma unroll
        for (int j = 0; j < 2; j++)
            wmma::load_matrix_sync(fb[j], sB + wn * 32 + j * 16, SMB);
#pragma unroll
        for (int i = 0; i < 4; i++) {
            wmma::fragment<wmma::matrix_a, 16, 16, 16, __half, wmma::row_major> fa;
            wmma::load_matrix_sync(fa, sA + (wm * 64 + i * 16) * SMA, SMA);
#pragma unroll
            for (int j = 0; j < 2; j++)
                wmma::mma_sync(fc[i][j], fa, fb[j], fc[i][j]);
        }
    }
    __syncthreads();

#pragma unroll
    for (int i = 0; i < 4; i++)
#pragma unroll
        for (int j = 0; j < 2; j++)
            wmma::store_matrix_sync(sC + (size_t)(wm * 64 + i * 16) * SMC + wn * 32 + j * 16,
                                    fc[i][j], SMC, wmma::mem_row_major);
    __syncthreads();

    int row = tid >> 1, cbase = (tid & 1) * 64;
    if (bm + row < M) {
        __half* cp = C + (size_t)(bm + row) * N + bn + cbase;
        const float* crow = sC + row * SMC + cbase;
#pragma unroll
        for (int c = 0; c < 64; c += 8) {
            __half2 p0 = __floats2half2_rn(crow[c + 0], crow[c + 1]);
            __half2 p1 = __floats2half2_rn(crow[c + 2], crow[c + 3]);
            __half2 p2 = __floats2half2_rn(crow[c + 4], crow[c + 5]);
            __half2 p3 = __floats2half2_rn(crow[c + 6], crow[c + 7]);
            *(uint4*)(cp + c) = make_uint4(*(unsigned*)&p0, *(unsigned*)&p1,
                                           *(unsigned*)&p2, *(unsigned*)&p3);
        }
    }

    {
        float ps = 0.f, pd = 0.f;
        const float* arow = a_src + head * 128 + cbase;
        const float* drow = a_dst + head * 128 + cbase;
        const float* crow = sC + row * SMC + cbase;
#pragma unroll 16
        for (int c = 0; c < 64; c++) {
            float cv = crow[c];
            ps += cv * arow[c];
            pd += cv * drow[c];
        }
        ps += __shfl_xor_sync(0xffffffffu, ps, 1);
        pd += __shfl_xor_sync(0xffffffffu, pd, 1);
        if ((tid & 1) == 0 && bm + row < M) {
            ssrc[(bm + row) * H + head] = ps;
            sdst[(bm + row) * H + head] = pd;
        }
    }
}

// ---------------- layer0 fused softmax+aggregate+bias+ELU (fp16 out) -----------
__global__ __launch_bounds__(128) void msg0f(const int* __restrict__ off,
                                             const int* __restrict__ csrc,
                                             const float* __restrict__ ssrc,
                                             const float* __restrict__ sdst,
                                             const __half* __restrict__ h,
                                             const float* __restrict__ b0,
                                             __half* __restrict__ out,
                                             int nodeBase, int nodeEnd) {
    int node = nodeBase + blockIdx.x * 4 + (threadIdx.x >> 5);
    if (node >= nodeEnd) return;
    int lane = threadIdx.x & 31;
    int head = lane >> 4;
    int begin = off[node], end = off[node + 1];
    float sd = sdst[node * 2 + head];
    const __half* hb = h + lane * 8;
    float2 acc[4][4];
#pragma unroll
    for (int q = 0; q < 4; q++)
#pragma unroll
        for (int k = 0; k < 4; k++) acc[q][k] = make_float2(0.f, 0.f);
    float wsum = 0.f;
    int j = begin;
    for (; j + 4 <= end; j += 4) {
        int s0 = csrc[j], s1 = csrc[j + 1], s2 = csrc[j + 2], s3 = csrc[j + 3];
        float a0 = __expf(lrelu(ssrc[s0 * 2 + head] + sd));
        float a1 = __expf(lrelu(ssrc[s1 * 2 + head] + sd));
        float a2 = __expf(lrelu(ssrc[s2 * 2 + head] + sd));
        float a3 = __expf(lrelu(ssrc[s3 * 2 + head] + sd));
        wsum += (a0 + a1) + (a2 + a3);
        uint4 u0 = *(const uint4*)(hb + (size_t)s0 * 256);
        uint4 u1 = *(const uint4*)(hb + (size_t)s1 * 256);
        uint4 u2 = *(const uint4*)(hb + (size_t)s2 * 256);
        uint4 u3 = *(const uint4*)(hb + (size_t)s3 * 256);
#define ACC0(q, u, a)                                                     \
        {                                                                 \
            float2 f0 = __half22float2(*(const __half2*)&u.x);            \
            float2 f1 = __half22float2(*(const __half2*)&u.y);            \
            float2 f2 = __half22float2(*(const __half2*)&u.z);            \
            float2 f3 = __half22float2(*(const __half2*)&u.w);            \
            acc[q][0].x += a * f0.x; acc[q][0].y += a * f0.y;             \
            acc[q][1].x += a * f1.x; acc[q][1].y += a * f1.y;             \
            acc[q][2].x += a * f2.x; acc[q][2].y += a * f2.y;             \
            acc[q][3].x += a * f3.x; acc[q][3].y += a * f3.y;             \
        }
        ACC0(0, u0, a0) ACC0(1, u1, a1) ACC0(2, u2, a2) ACC0(3, u3, a3)
    }
    for (; j < end; j++) {
        int s0 = csrc[j];
        float a0 = __expf(lrelu(ssrc[s0 * 2 + head] + sd));
        wsum += a0;
        uint4 u0 = *(const uint4*)(hb + (size_t)s0 * 256);
        ACC0(0, u0, a0)
    }
#undef ACC0
    float r = 1.f / wsum;
    float4 bbA = *(const float4*)(b0 + lane * 8);
    float4 bbB = *(const float4*)(b0 + lane * 8 + 4);
    float v[8];
    v[0] = (acc[0][0].x + acc[1][0].x + acc[2][0].x + acc[3][0].x) * r + bbA.x;
    v[1] = (acc[0][0].y + acc[1][0].y + acc[2][0].y + acc[3][0].y) * r + bbA.y;
    v[2] = (acc[0][1].x + acc[1][1].x + acc[2][1].x + acc[3][1].x) * r + bbA.z;
    v[3] = (acc[0][1].y + acc[1][1].y + acc[2][1].y + acc[3][1].y) * r + bbA.w;
    v[4] = (acc[0][2].x + acc[1][2].x + acc[2][2].x + acc[3][2].x) * r + bbB.x;
    v[5] = (acc[0][2].y + acc[1][2].y + acc[2][2].y + acc[3][2].y) * r + bbB.y;
    v[6] = (acc[0][3].x + acc[1][3].x + acc[2][3].x + acc[3][3].x) * r + bbB.z;
    v[7] = (acc[0][3].y + acc[1][3].y + acc[2][3].y + acc[3][3].y) * r + bbB.w;
#pragma unroll
    for (int k = 0; k < 8; k++) v[k] = v[k] > 0.f ? v[k] : (expf(v[k]) - 1.f);
    __half2 p0 = __floats2half2_rn(v[0], v[1]);
    __half2 p1 = __floats2half2_rn(v[2], v[3]);
    __half2 p2 = __floats2half2_rn(v[4], v[5]);
    __half2 p3 = __floats2half2_rn(v[6], v[7]);
    *(uint4*)(out + (size_t)node * 256 + lane * 8) =
        make_uint4(*(unsigned*)&p0, *(unsigned*)&p1, *(unsigned*)&p2, *(unsigned*)&p3);
}

// ---------------- layer1 fused softmax+aggregate+residual+bias -----------------
__global__ __launch_bounds__(128) void msg1f(const int* __restrict__ off,
                                             const int* __restrict__ csrc,
                                             const float* __restrict__ ssrc,
                                             const float* __restrict__ sdst,
                                             const __half* __restrict__ h,
                                             const float* __restrict__ x,
                                             const float* __restrict__ b1,
                                             float* __restrict__ out) {
    int node = blockIdx.x * 4 + (threadIdx.x >> 5);
    if (node >= NN) return;
    int lane = threadIdx.x & 31;
    int begin = off[node], end = off[node + 1];
    float sd = sdst[node];
    const __half* hb = h + lane * 4;
    float2 acc[4][2];
#pragma unroll
    for (int q = 0; q < 4; q++) {
        acc[q][0] = make_float2(0.f, 0.f);
        acc[q][1] = make_float2(0.f, 0.f);
    }
    float wsum = 0.f;
    int j = begin;
    for (; j + 4 <= end; j += 4) {
        int s0 = csrc[j], s1 = csrc[j + 1], s2 = csrc[j + 2], s3 = csrc[j + 3];
        float a0 = __expf(lrelu(ssrc[s0] + sd));
        float a1 = __expf(lrelu(ssrc[s1] + sd));
        float a2 = __expf(lrelu(ssrc[s2] + sd));
        float a3 = __expf(lrelu(ssrc[s3] + sd));
        wsum += (a0 + a1) + (a2 + a3);
        uint2 u0 = *(const uint2*)(hb + (size_t)s0 * 128);
        uint2 u1 = *(const uint2*)(hb + (size_t)s1 * 128);
        uint2 u2 = *(const uint2*)(hb + (size_t)s2 * 128);
        uint2 u3 = *(const uint2*)(hb + (size_t)s3 * 128);
#define ACC1(q, u, a)                                                     \
        {                                                                 \
            float2 f0 = __half22float2(*(const __half2*)&u.x);            \
            float2 f1 = __half22float2(*(const __half2*)&u.y);            \
            acc[q][0].x += a * f0.x; acc[q][0].y += a * f0.y;             \
            acc[q][1].x += a * f1.x; acc[q][1].y += a * f1.y;             \
        }
        ACC1(0, u0, a0) ACC1(1, u1, a1) ACC1(2, u2, a2) ACC1(3, u3, a3)
    }
    for (; j < end; j++) {
        int s0 = csrc[j];
        float a0 = __expf(lrelu(ssrc[s0] + sd));
        wsum += a0;
        uint2 u0 = *(const uint2*)(hb + (size_t)s0 * 128);
        ACC1(0, u0, a0)
    }
#undef ACC1
    float r = 1.f / wsum;
    float4 xb = *(const float4*)(x + (size_t)node * 128 + lane * 4);
    float4 bb = *(const float4*)(b1 + lane * 4);
    float4 o;
    o.x = (acc[0][0].x + acc[1][0].x + acc[2][0].x + acc[3][0].x) * r + xb.x + bb.x;
    o.y = (acc[0][0].y + acc[1][0].y + acc[2][0].y + acc[3][0].y) * r + xb.y + bb.y;
    o.z = (acc[0][1].x + acc[1][1].x + acc[2][1].x + acc[3][1].x) * r + xb.z + bb.z;
    o.w = (acc[0][1].y + acc[1][1].y + acc[2][1].y + acc[3][1].y) * r + xb.w + bb.w;
    *(float4*)(out + (size_t)node * 128 + lane * 4) = o;
}

// ---------------- launch -------------------------------------------------------
extern "C" void kernel_launch(void* const* d_in, const int* in_sizes, int n_in,
                              void* d_out, int out_size) {
    const float* x      = (const float*)d_in[0];
    const float* W0     = (const float*)d_in[1];
    const float* a_src0 = (const float*)d_in[2];
    const float* a_dst0 = (const float*)d_in[3];
    const float* b0     = (const float*)d_in[4];
    const float* W1     = (const float*)d_in[5];
    const float* a_src1 = (const float*)d_in[6];
    const float* a_dst1 = (const float*)d_in[7];
    const float* b1     = (const float*)d_in[8];
    const int*   ei     = (const int*)d_in[9];
    int E0 = in_sizes[9] / 2;
    int Etot = E0 + NN;
    const int* src = ei;
    const int* dst = ei + E0;
    float* out = (float*)d_out;

    __half *xh, *W0h, *W1h, *h0, *out0h, *h1;
    float *ssrc0, *sdst0, *ssrc1, *sdst1;
    int *cnt, *off, *cursor, *csrc;
    cudaGetSymbolAddress((void**)&xh, g_xh);
    cudaGetSymbolAddress((void**)&W0h, g_W0h);
    cudaGetSymbolAddress((void**)&W1h, g_W1h);
    cudaGetSymbolAddress((void**)&h0, g_h0);
    cudaGetSymbolAddress((void**)&out0h, g_out0h);
    cudaGetSymbolAddress((void**)&h1, g_h1);
    cudaGetSymbolAddress((void**)&ssrc0, g_ssrc0);
    cudaGetSymbolAddress((void**)&sdst0, g_sdst0);
    cudaGetSymbolAddress((void**)&ssrc1, g_ssrc1);
    cudaGetSymbolAddress((void**)&sdst1, g_sdst1);
    cudaGetSymbolAddress((void**)&cnt, g_cnt);
    cudaGetSymbolAddress((void**)&off, g_off);
    cudaGetSymbolAddress((void**)&cursor, g_cursor);
    cudaGetSymbolAddress((void**)&csrc, g_csrc);

    cudaFuncSetAttribute(gemmW, cudaFuncAttributeMaxDynamicSharedMemorySize, GEMM_SMEM);

    cudaStream_t sB;
    cudaStreamCreateWithFlags(&sB, cudaStreamNonBlocking);
    cudaEvent_t evFork, evB, evM0[NCHUNK - 1], evG1;
    cudaEventCreateWithFlags(&evFork, cudaEventDisableTiming);
    cudaEventCreateWithFlags(&evB, cudaEventDisableTiming);
    for (int i = 0; i < NCHUNK - 1; i++)
        cudaEventCreateWithFlags(&evM0[i], cudaEventDisableTiming);
    cudaEventCreateWithFlags(&evG1, cudaEventDisableTiming);

    cudaEventRecord(evFork, 0);
    cudaStreamWaitEvent(sB, evFork, 0);

    // ---- CSR build on side stream (overlaps conversions + gemm0) ----
    filli<<<(NN + 255) / 256, 256, 0, sB>>>(cnt, NN, 1);
    histK<<<(E0 + 255) / 256, 256, 0, sB>>>(dst, E0, cnt);
    scanK<<<1, 1024, 0, sB>>>(cnt, off, cursor);
    scatterK<<<(Etot + 255) / 256, 256, 0, sB>>>(src, dst, E0, Etot, cursor, csrc);
    cudaEventRecord(evB, sB);

    // ---- fp16 conversions + layer0 GEMM on main ----
    f2h<<<(NN * 128 / 4 + 255) / 256, 256>>>(x, xh, NN * 128 / 4);
    f2h<<<(128 * 256 / 4 + 255) / 256, 256>>>(W0, W0h, 128 * 256 / 4);
    f2h<<<(256 * 128 / 4 + 255) / 256, 256>>>(W1, W1h, 256 * 128 / 4);
    gemmW<<<dim3(2, (NN + 127) / 128), 256, GEMM_SMEM>>>(
        xh, W0h, h0, a_src0, a_dst0, ssrc0, sdst0, NN, 256, 128, 2, 0);
    cudaStreamWaitEvent(0, evB, 0);

    // ---- msg0f / gemm1 chunked pipeline ----
    // main: msg0f c0..c3 ; side: gemm1 c0..c2 (each released by its msg0f chunk);
    // gemm1 c3 runs on main after msg0f c3.
    for (int c = 0; c < NCHUNK; c++) {
        int nb = c * CH;
        int ne = (c == NCHUNK - 1) ? NN : nb + CH;
        msg0f<<<(ne - nb + 3) / 4, 128>>>(off, csrc, ssrc0, sdst0, h0, b0, out0h,
                                          nb, ne);
        if (c < NCHUNK - 1) {
            cudaEventRecord(evM0[c], 0);
            cudaStreamWaitEvent(sB, evM0[c], 0);
            gemmW<<<dim3(1, (ne - nb + 127) / 128), 256, GEMM_SMEM, sB>>>(
                out0h, W1h, h1, a_src1, a_dst1, ssrc1, sdst1, NN, 128, 256, 1, nb);
        } else {
            gemmW<<<dim3(1, (ne - nb + 127) / 128), 256, GEMM_SMEM>>>(
                out0h, W1h, h1, a_src1, a_dst1, ssrc1, sdst1, NN, 128, 256, 1, nb);
        }
    }
    cudaEventRecord(evG1, sB);
    cudaStreamWaitEvent(0, evG1, 0);

    // ---- msg1f (full) ----
    msg1f<<<(NN + 3) / 4, 128>>>(off, csrc, ssrc1, sdst1, h1, x, b1, out);

    cudaEventDestroy(evFork);
    cudaEventDestroy(evB);
    for (int i = 0; i < NCHUNK - 1; i++) cudaEventDestroy(evM0[i]);
    cudaEventDestroy(evG1);
    cudaStreamDestroy(sB);
}

// round 16
// speedup vs baseline: 1.0869x; 1.0869x over previous
#include <cuda_runtime.h>
#include <cuda_fp16.h>
#include <mma.h>
#include <math.h>

using namespace nvcuda;

#define NN 50000
#define EMAXE 900000
#define SPLIT 25088   // node split for msg0f/gemm1 pipelining (multiple of 128)

// ---------------- scratch (device globals) -----------------------------------
__device__ __half g_xh[(size_t)NN * 128];    // x in fp16 (GEMM0 A)
__device__ __half g_W0h[128 * 256];
__device__ __half g_W1h[256 * 128];
__device__ __half g_h0[(size_t)NN * 256];    // layer0 features, fp16
__device__ __half g_out0h[(size_t)NN * 256]; // layer0 output, fp16 (GEMM1 A)
__device__ __half g_h1[(size_t)NN * 128];    // layer1 features, fp16
__device__ float  g_ssrc0[NN * 2];
__device__ float  g_sdst0[NN * 2];
__device__ float  g_ssrc1[NN];
__device__ float  g_sdst1[NN];
__device__ int    g_cnt[NN];
__device__ int    g_off[NN + 1];
__device__ int    g_cursor[NN];
__device__ int    g_csrc[EMAXE];

__device__ __forceinline__ float lrelu(float v) { return v > 0.f ? v : 0.2f * v; }

// ---------------- fp32 -> fp16 convert ----------------------------------------
__global__ void f2h(const float* __restrict__ in, __half* __restrict__ out, int n4) {
    int i = blockIdx.x * blockDim.x + threadIdx.x;
    if (i < n4) {
        float4 v = ((const float4*)in)[i];
        __half2 p0 = __floats2half2_rn(v.x, v.y);
        __half2 p1 = __floats2half2_rn(v.z, v.w);
        ((uint2*)out)[i] = make_uint2(*(unsigned*)&p0, *(unsigned*)&p1);
    }
}

// ---------------- CSR build ---------------------------------------------------
__global__ void filli(int* __restrict__ p, int n, int v) {
    int i = blockIdx.x * blockDim.x + threadIdx.x;
    if (i < n) p[i] = v;
}

__global__ void histK(const int* __restrict__ dst, int E0, int* __restrict__ cnt) {
    int e = blockIdx.x * blockDim.x + threadIdx.x;
    if (e < E0) atomicAdd(&cnt[dst[e]], 1);
}

__global__ __launch_bounds__(1024) void scanK(const int* __restrict__ cnt,
                                              int* __restrict__ off,
                                              int* __restrict__ cursor) {
    __shared__ int wsum[32];
    __shared__ int s_carry;
    int tid = threadIdx.x;
    int lane = tid & 31, warp = tid >> 5;
    if (tid == 0) s_carry = 0;
    __syncthreads();
    for (int base = 0; base < NN; base += 1024) {
        int i = base + tid;
        int v = (i < NN) ? cnt[i] : 0;
        int s = v;
#pragma unroll
        for (int o = 1; o < 32; o <<= 1) {
            int t = __shfl_up_sync(0xffffffffu, s, o);
            if (lane >= o) s += t;
        }
        if (lane == 31) wsum[warp] = s;
        __syncthreads();
        if (warp == 0) {
            int ws = wsum[lane];
#pragma unroll
            for (int o = 1; o < 32; o <<= 1) {
                int t = __shfl_up_sync(0xffffffffu, ws, o);
                if (lane >= o) ws += t;
            }
            wsum[lane] = ws;
        }
        __syncthreads();
        int excl = s - v + (warp ? wsum[warp - 1] : 0) + s_carry;
        if (i < NN) { off[i] = excl; cursor[i] = excl; }
        __syncthreads();
        if (tid == 1023) s_carry = excl + v;
        __syncthreads();
    }
    if (tid == 0) off[NN] = s_carry;
}

__global__ void scatterK(const int* __restrict__ src, const int* __restrict__ dst,
                         int E0, int Etot, int* __restrict__ cursor,
                         int* __restrict__ csrc) {
    int e = blockIdx.x * blockDim.x + threadIdx.x;
    if (e >= Etot) return;
    int s, d;
    if (e < E0) { s = src[e]; d = dst[e]; } else { s = d = e - E0; }
    int p = atomicAdd(&cursor[d], 1);
    csrc[p] = s;
}

// ---------------- tensor-core GEMM + fused scores ------------------------------
// A/B fp16, acc fp32, C out fp16. 128x128 tile, 8 warps (64x32 each),
// single-buffered smem (R12-proven). Epilogue stages fp32 C tile in smem for
// the a_src/a_dst score reduction and the fp16 C store.
#define SMA 24
#define SMB 136
#define SMC 132
#define GEMM_SMEM (128 * SMC * 4)

__global__ __launch_bounds__(256) void gemmW(const __half* __restrict__ A,
                                             const __half* __restrict__ B,
                                             __half* __restrict__ C,
                                             const float* __restrict__ a_src,
                                             const float* __restrict__ a_dst,
                                             float* __restrict__ ssrc,
                                             float* __restrict__ sdst,
                                             int M, int N, int K, int H,
                                             int rowBase) {
    extern __shared__ char smem[];
    __half* sA = (__half*)smem;                    // [128][SMA]
    __half* sB = (__half*)(smem + 128 * SMA * 2);  // [16][SMB]
    float*  sC = (float*)smem;                     // [128][SMC] (post-loop)

    int bm = rowBase + blockIdx.y * 128, bn = blockIdx.x * 128;
    int head = blockIdx.x;
    int tid = threadIdx.x;
    int wid = tid >> 5;
    int wm = wid >> 2, wn = wid & 3;

    wmma::fragment<wmma::accumulator, 16, 16, 16, float> fc[4][2];
#pragma unroll
    for (int i = 0; i < 4; i++)
#pragma unroll
        for (int j = 0; j < 2; j++) wmma::fill_fragment(fc[i][j], 0.f);

    int raA = tid >> 1, caA = (tid & 1) * 8;
    int raB = tid >> 4, caB = (tid & 15) * 8;

    for (int k0 = 0; k0 < K; k0 += 16) {
        __syncthreads();
        {
            uint4 v = make_uint4(0, 0, 0, 0);
            if (bm + raA < M)
                v = *(const uint4*)(A + (size_t)(bm + raA) * K + k0 + caA);
            *(uint4*)(sA + raA * SMA + caA) = v;
            uint4 w = *(const uint4*)(B + (size_t)(k0 + raB) * N + bn + caB);
            *(uint4*)(sB + raB * SMB + caB) = w;
        }
        __syncthreads();
        wmma::fragment<wmma::matrix_b, 16, 16, 16, __half, wmma::row_major> fb[2];
#pragma unroll
        for (int j = 0; j < 2; j++)
            wmma::load_matrix_sync(fb[j], sB + wn * 32 + j * 16, SMB);
#pragma unroll
        for (int i = 0; i < 4; i++) {
            wmma::fragment<wmma::matrix_a, 16, 16, 16, __half, wmma::row_major> fa;
            wmma::load_matrix_sync(fa, sA + (wm * 64 + i * 16) * SMA, SMA);
#pragma unroll
            for (int j = 0; j < 2; j++)
                wmma::mma_sync(fc[i][j], fa, fb[j], fc[i][j]);
        }
    }
    __syncthreads();

#pragma unroll
    for (int i = 0; i < 4; i++)
#pragma unroll
        for (int j = 0; j < 2; j++)
            wmma::store_matrix_sync(sC + (size_t)(wm * 64 + i * 16) * SMC + wn * 32 + j * 16,
                                    fc[i][j], SMC, wmma::mem_row_major);
    __syncthreads();

    int row = tid >> 1, cbase = (tid & 1) * 64;
    if (bm + row < M) {
        __half* cp = C + (size_t)(bm + row) * N + bn + cbase;
        const float* crow = sC + row * SMC + cbase;
#pragma unroll
        for (int c = 0; c < 64; c += 8) {
            __half2 p0 = __floats2half2_rn(crow[c + 0], crow[c + 1]);
            __half2 p1 = __floats2half2_rn(crow[c + 2], crow[c + 3]);
            __half2 p2 = __floats2half2_rn(crow[c + 4], crow[c + 5]);
            __half2 p3 = __floats2half2_rn(crow[c + 6], crow[c + 7]);
            *(uint4*)(cp + c) = make_uint4(*(unsigned*)&p0, *(unsigned*)&p1,
                                           *(unsigned*)&p2, *(unsigned*)&p3);
        }
    }

    {
        float ps = 0.f, pd = 0.f;
        const float* arow = a_src + head * 128 + cbase;
        const float* drow = a_dst + head * 128 + cbase;
        const float* crow = sC + row * SMC + cbase;
#pragma unroll 16
        for (int c = 0; c < 64; c++) {
            float cv = crow[c];
            ps += cv * arow[c];
            pd += cv * drow[c];
        }
        ps += __shfl_xor_sync(0xffffffffu, ps, 1);
        pd += __shfl_xor_sync(0xffffffffu, pd, 1);
        if ((tid & 1) == 0 && bm + row < M) {
            ssrc[(bm + row) * H + head] = ps;
            sdst[(bm + row) * H + head] = pd;
        }
    }
}

// ---------------- layer0 fused softmax+aggregate+bias+ELU (fp16 out) -----------
__global__ __launch_bounds__(128) void msg0f(const int* __restrict__ off,
                                             const int* __restrict__ csrc,
                                             const float* __restrict__ ssrc,
                                             const float* __restrict__ sdst,
                                             const __half* __restrict__ h,
                                             const float* __restrict__ b0,
                                             __half* __restrict__ out,
                                             int nodeBase, int nodeEnd) {
    int node = nodeBase + blockIdx.x * 4 + (threadIdx.x >> 5);
    if (node >= nodeEnd) return;
    int lane = threadIdx.x & 31;
    int head = lane >> 4;
    int begin = off[node], end = off[node + 1];
    float sd = sdst[node * 2 + head];
    const __half* hb = h + lane * 8;
    float2 acc[4][4];
#pragma unroll
    for (int q = 0; q < 4; q++)
#pragma unroll
        for (int k = 0; k < 4; k++) acc[q][k] = make_float2(0.f, 0.f);
    float wsum = 0.f;
    int j = begin;
    for (; j + 4 <= end; j += 4) {
        int s0 = csrc[j], s1 = csrc[j + 1], s2 = csrc[j + 2], s3 = csrc[j + 3];
        float a0 = __expf(lrelu(ssrc[s0 * 2 + head] + sd));
        float a1 = __expf(lrelu(ssrc[s1 * 2 + head] + sd));
        float a2 = __expf(lrelu(ssrc[s2 * 2 + head] + sd));
        float a3 = __expf(lrelu(ssrc[s3 * 2 + head] + sd));
        wsum += (a0 + a1) + (a2 + a3);
        uint4 u0 = *(const uint4*)(hb + (size_t)s0 * 256);
        uint4 u1 = *(const uint4*)(hb + (size_t)s1 * 256);
        uint4 u2 = *(const uint4*)(hb + (size_t)s2 * 256);
        uint4 u3 = *(const uint4*)(hb + (size_t)s3 * 256);
#define ACC0(q, u, a)                                                     \
        {                                                                 \
            float2 f0 = __half22float2(*(const __half2*)&u.x);            \
            float2 f1 = __half22float2(*(const __half2*)&u.y);            \
            float2 f2 = __half22float2(*(const __half2*)&u.z);            \
            float2 f3 = __half22float2(*(const __half2*)&u.w);            \
            acc[q][0].x += a * f0.x; acc[q][0].y += a * f0.y;             \
            acc[q][1].x += a * f1.x; acc[q][1].y += a * f1.y;             \
            acc[q][2].x += a * f2.x; acc[q][2].y += a * f2.y;             \
            acc[q][3].x += a * f3.x; acc[q][3].y += a * f3.y;             \
        }
        ACC0(0, u0, a0) ACC0(1, u1, a1) ACC0(2, u2, a2) ACC0(3, u3, a3)
    }
    for (; j < end; j++) {
        int s0 = csrc[j];
        float a0 = __expf(lrelu(ssrc[s0 * 2 + head] + sd));
        wsum += a0;
        uint4 u0 = *(const uint4*)(hb + (size_t)s0 * 256);
        ACC0(0, u0, a0)
    }
#undef ACC0
    float r = 1.f / wsum;
    float4 bbA = *(const float4*)(b0 + lane * 8);
    float4 bbB = *(const float4*)(b0 + lane * 8 + 4);
    float v[8];
    v[0] = (acc[0][0].x + acc[1][0].x + acc[2][0].x + acc[3][0].x) * r + bbA.x;
    v[1] = (acc[0][0].y + acc[1][0].y + acc[2][0].y + acc[3][0].y) * r + bbA.y;
    v[2] = (acc[0][1].x + acc[1][1].x + acc[2][1].x + acc[3][1].x) * r + bbA.z;
    v[3] = (acc[0][1].y + acc[1][1].y + acc[2][1].y + acc[3][1].y) * r + bbA.w;
    v[4] = (acc[0][2].x + acc[1][2].x + acc[2][2].x + acc[3][2].x) * r + bbB.x;
    v[5] = (acc[0][2].y + acc[1][2].y + acc[2][2].y + acc[3][2].y) * r + bbB.y;
    v[6] = (acc[0][3].x + acc[1][3].x + acc[2][3].x + acc[3][3].x) * r + bbB.z;
    v[7] = (acc[0][3].y + acc[1][3].y + acc[2][3].y + acc[3][3].y) * r + bbB.w;
#pragma unroll
    for (int k = 0; k < 8; k++) v[k] = v[k] > 0.f ? v[k] : (expf(v[k]) - 1.f);
    __half2 p0 = __floats2half2_rn(v[0], v[1]);
    __half2 p1 = __floats2half2_rn(v[2], v[3]);
    __half2 p2 = __floats2half2_rn(v[4], v[5]);
    __half2 p3 = __floats2half2_rn(v[6], v[7]);
    *(uint4*)(out + (size_t)node * 256 + lane * 8) =
        make_uint4(*(unsigned*)&p0, *(unsigned*)&p1, *(unsigned*)&p2, *(unsigned*)&p3);
}

// ---------------- layer1 fused softmax+aggregate+residual+bias -----------------
// 1 warp/node, half-warp per edge: lanes 0-15 take even CSR slots, 16-31 odd.
// Each sub-lane gathers uint4 (16B); cross-half combine once at the end.
__global__ __launch_bounds__(128) void msg1f(const int* __restrict__ off,
                                             const int* __restrict__ csrc,
                                             const float* __restrict__ ssrc,
                                             const float* __restrict__ sdst,
                                             const __half* __restrict__ h,
                                             const float* __restrict__ x,
                                             const float* __restrict__ b1,
                                             float* __restrict__ out) {
    int node = blockIdx.x * 4 + (threadIdx.x >> 5);
    if (node >= NN) return;
    int lane = threadIdx.x & 31;
    int half = lane >> 4;     // which edge-parity this lane serves
    int sub = lane & 15;      // feature chunk within the 128-half row
    int begin = off[node], end = off[node + 1];
    float sd = sdst[node];
    const __half* hb = h + sub * 8;
    float2 acc[2][4];
#pragma unroll
    for (int q = 0; q < 2; q++)
#pragma unroll
        for (int k = 0; k < 4; k++) acc[q][k] = make_float2(0.f, 0.f);
    float wsum = 0.f;
#define ACC1(q, u, a)                                                     \
    {                                                                     \
        float2 f0 = __half22float2(*(const __half2*)&(u).x);              \
        float2 f1 = __half22float2(*(const __half2*)&(u).y);              \
        float2 f2 = __half22float2(*(const __half2*)&(u).z);              \
        float2 f3 = __half22float2(*(const __half2*)&(u).w);              \
        acc[q][0].x += (a) * f0.x; acc[q][0].y += (a) * f0.y;             \
        acc[q][1].x += (a) * f1.x; acc[q][1].y += (a) * f1.y;             \
        acc[q][2].x += (a) * f2.x; acc[q][2].y += (a) * f2.y;             \
        acc[q][3].x += (a) * f3.x; acc[q][3].y += (a) * f3.y;             \
    }
    int j = begin + half;
    for (; j + 2 < end; j += 4) {   // this half handles j and j+2
        int s0 = csrc[j], s1 = csrc[j + 2];
        float a0 = __expf(lrelu(ssrc[s0] + sd));
        float a1 = __expf(lrelu(ssrc[s1] + sd));
        wsum += a0 + a1;
        uint4 u0 = *(const uint4*)(hb + (size_t)s0 * 128);
        uint4 u1 = *(const uint4*)(hb + (size_t)s1 * 128);
        ACC1(0, u0, a0)
        ACC1(1, u1, a1)
    }
    for (; j < end; j += 2) {
        int s0 = csrc[j];
        float a0 = __expf(lrelu(ssrc[s0] + sd));
        wsum += a0;
        uint4 u0 = *(const uint4*)(hb + (size_t)s0 * 128);
        ACC1(0, u0, a0)
    }
#undef ACC1
    // combine the two edge-parity halves (features duplicated at lane ^ 16)
    float v[8];
    v[0] = acc[0][0].x + acc[1][0].x;
    v[1] = acc[0][0].y + acc[1][0].y;
    v[2] = acc[0][1].x + acc[1][1].x;
    v[3] = acc[0][1].y + acc[1][1].y;
    v[4] = acc[0][2].x + acc[1][2].x;
    v[5] = acc[0][2].y + acc[1][2].y;
    v[6] = acc[0][3].x + acc[1][3].x;
    v[7] = acc[0][3].y + acc[1][3].y;
#pragma unroll
    for (int k = 0; k < 8; k++) v[k] += __shfl_xor_sync(0xffffffffu, v[k], 16);
    wsum += __shfl_xor_sync(0xffffffffu, wsum, 16);
    float r = 1.f / wsum;
    // lane writes float4 at feature offset sub*8 + half*4 (coalesced, no dup)
    int fo = sub * 8 + half * 4;
    float4 xb = *(const float4*)(x + (size_t)node * 128 + fo);
    float4 bb = *(const float4*)(b1 + fo);
    float4 o;
    o.x = v[half * 4 + 0] * r + xb.x + bb.x;
    o.y = v[half * 4 + 1] * r + xb.y + bb.y;
    o.z = v[half * 4 + 2] * r + xb.z + bb.z;
    o.w = v[half * 4 + 3] * r + xb.w + bb.w;
    *(float4*)(out + (size_t)node * 128 + fo) = o;
}

// ---------------- launch -------------------------------------------------------
extern "C" void kernel_launch(void* const* d_in, const int* in_sizes, int n_in,
                              void* d_out, int out_size) {
    const float* x      = (const float*)d_in[0];
    const float* W0     = (const float*)d_in[1];
    const float* a_src0 = (const float*)d_in[2];
    const float* a_dst0 = (const float*)d_in[3];
    const float* b0     = (const float*)d_in[4];
    const float* W1     = (const float*)d_in[5];
    const float* a_src1 = (const float*)d_in[6];
    const float* a_dst1 = (const float*)d_in[7];
    const float* b1     = (const float*)d_in[8];
    const int*   ei     = (const int*)d_in[9];
    int E0 = in_sizes[9] / 2;
    int Etot = E0 + NN;
    const int* src = ei;
    const int* dst = ei + E0;
    float* out = (float*)d_out;

    __half *xh, *W0h, *W1h, *h0, *out0h, *h1;
    float *ssrc0, *sdst0, *ssrc1, *sdst1;
    int *cnt, *off, *cursor, *csrc;
    cudaGetSymbolAddress((void**)&xh, g_xh);
    cudaGetSymbolAddress((void**)&W0h, g_W0h);
    cudaGetSymbolAddress((void**)&W1h, g_W1h);
    cudaGetSymbolAddress((void**)&h0, g_h0);
    cudaGetSymbolAddress((void**)&out0h, g_out0h);
    cudaGetSymbolAddress((void**)&h1, g_h1);
    cudaGetSymbolAddress((void**)&ssrc0, g_ssrc0);
    cudaGetSymbolAddress((void**)&sdst0, g_sdst0);
    cudaGetSymbolAddress((void**)&ssrc1, g_ssrc1);
    cudaGetSymbolAddress((void**)&sdst1, g_sdst1);
    cudaGetSymbolAddress((void**)&cnt, g_cnt);
    cudaGetSymbolAddress((void**)&off, g_off);
    cudaGetSymbolAddress((void**)&cursor, g_cursor);
    cudaGetSymbolAddress((void**)&csrc, g_csrc);

    cudaFuncSetAttribute(gemmW, cudaFuncAttributeMaxDynamicSharedMemorySize, GEMM_SMEM);

    cudaStream_t sB;
    cudaStreamCreateWithFlags(&sB, cudaStreamNonBlocking);
    cudaEvent_t evFork, evB, evM0a, evG1a;
    cudaEventCreateWithFlags(&evFork, cudaEventDisableTiming);
    cudaEventCreateWithFlags(&evB, cudaEventDisableTiming);
    cudaEventCreateWithFlags(&evM0a, cudaEventDisableTiming);
    cudaEventCreateWithFlags(&evG1a, cudaEventDisableTiming);

    cudaEventRecord(evFork, 0);
    cudaStreamWaitEvent(sB, evFork, 0);

    // ---- CSR build on side stream ----
    filli<<<(NN + 255) / 256, 256, 0, sB>>>(cnt, NN, 1);
    histK<<<(E0 + 255) / 256, 256, 0, sB>>>(dst, E0, cnt);
    scanK<<<1, 1024, 0, sB>>>(cnt, off, cursor);
    scatterK<<<(Etot + 255) / 256, 256, 0, sB>>>(src, dst, E0, Etot, cursor, csrc);
    cudaEventRecord(evB, sB);

    // ---- fp16 conversions + layer0 GEMM on main ----
    f2h<<<(NN * 128 / 4 + 255) / 256, 256>>>(x, xh, NN * 128 / 4);
    f2h<<<(128 * 256 / 4 + 255) / 256, 256>>>(W0, W0h, 128 * 256 / 4);
    f2h<<<(256 * 128 / 4 + 255) / 256, 256>>>(W1, W1h, 256 * 128 / 4);
    gemmW<<<dim3(2, (NN + 127) / 128), 256, GEMM_SMEM>>>(
        xh, W0h, h0, a_src0, a_dst0, ssrc0, sdst0, NN, 256, 128, 2, 0);
    cudaStreamWaitEvent(0, evB, 0);

    // ---- msg0f chunk A (nodes [0, SPLIT)) ----
    msg0f<<<SPLIT / 4, 128>>>(off, csrc, ssrc0, sdst0, h0, b0, out0h, 0, SPLIT);
    cudaEventRecord(evM0a, 0);

    // ---- gemm1 chunk A on side stream (rows [0, SPLIT)) — overlaps msg0f B ----
    cudaStreamWaitEvent(sB, evM0a, 0);
    gemmW<<<dim3(1, SPLIT / 128), 256, GEMM_SMEM, sB>>>(
        out0h, W1h, h1, a_src1, a_dst1, ssrc1, sdst1, NN, 128, 256, 1, 0);
    cudaEventRecord(evG1a, sB);

    // ---- msg0f chunk B (nodes [SPLIT, NN)) on main ----
    msg0f<<<(NN - SPLIT + 3) / 4, 128>>>(off, csrc, ssrc0, sdst0, h0, b0, out0h,
                                         SPLIT, NN);

    // ---- gemm1 chunk B on main (rows [SPLIT, NN)) ----
    gemmW<<<dim3(1, (NN - SPLIT + 127) / 128), 256, GEMM_SMEM>>>(
        out0h, W1h, h1, a_src1, a_dst1, ssrc1, sdst1, NN, 128, 256, 1, SPLIT);
    cudaStreamWaitEvent(0, evG1a, 0);

    // ---- msg1f (full) ----
    msg1f<<<(NN + 3) / 4, 128>>>(off, csrc, ssrc1, sdst1, h1, x, b1, out);

    cudaEventDestroy(evFork);
    cudaEventDestroy(evB);
    cudaEventDestroy(evM0a);
    cudaEventDestroy(evG1a);
    cudaStreamDestroy(sB);
}